// round 15
// baseline (speedup 1.0000x reference)
#include <cuda_runtime.h>
#include <cuda_fp16.h>
#include <cstdint>

// ===========================================================================
// Idefics3VisionEmbeddings via single-term fp16 mma.sync (base sm_103 ISA).
//   out[m,n] = sum_k A[m,k]*W[n,k] + bias[n] + pos_emb[pos[m], n]
//   M=21632 (=169*128 exact), N=1152 (=6*192), K=588 (pad 592)
// fp16 inputs (rn), fp32 accumulate. Norm-ratio error ~3e-4 < 1e-3.
// Block tile 128x192, 512 THREADS / 16 WARPS (warp tile 32x48), BK=64,
// 4-stage mbarrier ring + fragment double-buffering.
// Rationale (R10 post-mortem): regfile caps CTAs/SM at 1; only ~2 warps/SMSP
// left issue at 12%. 16 warps at ~115 regs/thread doubles latency coverage.
// ===========================================================================

namespace {
constexpr int kNPS = 26, kPatch = 14, kB = 32, kC = 3, kHW = 364, kD = 1152;
constexpr int kP = kNPS * kNPS;           // 676
constexpr int kK = kC * kPatch * kPatch;  // 588
constexpr int kM = kB * kP;               // 21632
constexpr int kKpad = 592;                // 37 * 16

constexpr int BM = 128, BN = 192, BK = 64;
constexpr int NCHUNK = 10;                // 9 full (64) + 1 partial (16)
constexpr int NT_THREADS = 512;

// smem rows: 64 fp16 = 128 B, padded to 144 B (16B-aligned; conflict-free)
constexpr int ROWB = 144;
constexpr int ARR_A = BM * ROWB;          // 18432 B
constexpr int ARR_B = BN * ROWB;          // 27648 B
constexpr int STAGE = ARR_A + ARR_B;      // 46080 B
constexpr int NSTG = 4;
constexpr int BARS = 64;                  // barrier block (full[4], empty[4])
constexpr int SMEM_SZ = BARS + NSTG * STAGE;
}  // namespace

// -------------------- device scratch (no cudaMalloc allowed) ---------------
__device__ __align__(256) __half g_Ah[(size_t)kM * kKpad];
__device__ __align__(256) __half g_Wh[(size_t)kD * kKpad];
__device__ int g_pos[kM];

// -------------------- helpers ----------------------------------------------
__device__ __forceinline__ uint32_t smem_u32(const void* p) {
    uint32_t a;
    asm("{ .reg .u64 t; cvta.to.shared.u64 t, %1; cvt.u32.u64 %0, t; }"
        : "=r"(a) : "l"(p));
    return a;
}
__device__ __forceinline__ void cp16(uint32_t dst, const void* src) {
    asm volatile("cp.async.cg.shared.global [%0], [%1], 16;"
                 :: "r"(dst), "l"(src) : "memory");
}
__device__ __forceinline__ void cp_mbar_arrive_noinc(uint32_t bar) {
    asm volatile("cp.async.mbarrier.arrive.noinc.shared::cta.b64 [%0];"
                 :: "r"(bar) : "memory");
}
__device__ __forceinline__ void mbar_init(uint32_t a, uint32_t cnt) {
    asm volatile("mbarrier.init.shared.b64 [%0], %1;" :: "r"(a), "r"(cnt) : "memory");
}
__device__ __forceinline__ void mbar_arrive(uint32_t a) {
    asm volatile("mbarrier.arrive.shared.b64 _, [%0];" :: "r"(a) : "memory");
}
__device__ __forceinline__ void mbar_wait(uint32_t a, uint32_t parity) {
    asm volatile(
        "{\n .reg .pred P;\n"
        "WL_%=:\n"
        " mbarrier.try_wait.parity.shared.b64 P, [%0], %1, 0x989680;\n"
        " @P bra WD_%=;\n"
        " bra WL_%=;\n"
        "WD_%=:\n}" :: "r"(a), "r"(parity) : "memory");
}
__device__ __forceinline__ void ldsm4(uint32_t* r, uint32_t addr) {
    asm volatile("ldmatrix.sync.aligned.m8n8.x4.shared.b16 {%0,%1,%2,%3}, [%4];"
                 : "=r"(r[0]), "=r"(r[1]), "=r"(r[2]), "=r"(r[3]) : "r"(addr));
}
__device__ __forceinline__ void mma16816(float* c, const uint32_t* a,
                                         const uint32_t* b) {
    asm volatile(
        "mma.sync.aligned.m16n8k16.row.col.f32.f16.f16.f32 "
        "{%0,%1,%2,%3}, {%4,%5,%6,%7}, {%8,%9}, {%0,%1,%2,%3};"
        : "+f"(c[0]), "+f"(c[1]), "+f"(c[2]), "+f"(c[3])
        : "r"(a[0]), "r"(a[1]), "r"(a[2]), "r"(a[3]), "r"(b[0]), "r"(b[1]));
}

// ---------------------------------------------------------------------------
// Position ids (exact fp32 replica of the reference). Mask dtype auto-detect:
// byte 1 nonzero => u8/bool layout (nb_w>=13 guarantees mask[0][0][1]==1).
// ---------------------------------------------------------------------------
__global__ void pos_kernel(const unsigned char* __restrict__ mraw) {
    const int b = blockIdx.x;
    const int t = threadIdx.x;
    __shared__ int s_bh[kNPS], s_bw[kNPS];
    __shared__ int s_nbh, s_nbw;

    const bool is_u8 = (mraw[1] != 0);
    auto mval = [&](int idx) -> int {
        return is_u8 ? (int)mraw[idx] : (int)mraw[4 * (size_t)idx];
    };
    const int base = b * kP;
    if (t == 0) {
        int nh = 0, nw = 0;
        for (int i = 0; i < kNPS; i++) nh += (mval(base + i * kNPS) != 0);
        for (int j = 0; j < kNPS; j++) nw += (mval(base + j) != 0);
        s_nbh = nh; s_nbw = nw;
    }
    __syncthreads();
    if (t < kNPS) {
        const float eps = 1.0f - 1e-6f;
        const float fh = ((float)t / (float)s_nbh) * eps;
        const float fw = ((float)t / (float)s_nbw) * eps;
        int ch = 0, cw = 0;
        #pragma unroll
        for (int j = 1; j < kNPS; j++) {
            const float bnd = (float)j / (float)kNPS;
            ch += (bnd <= fh) ? 1 : 0;
            cw += (bnd <= fw) ? 1 : 0;
        }
        s_bh[t] = ch; s_bw[t] = cw;
    }
    __syncthreads();
    for (int p = t; p < kP; p += blockDim.x) {
        const int ph = p / kNPS;
        const int pw = p - ph * kNPS;
        g_pos[base + p] = (mval(base + p) != 0) ? (s_bh[ph] * kNPS + s_bw[pw]) : 0;
    }
}

// ---------------------------------------------------------------------------
// Prep A: one block per (b, ph) strip. Coalesced 364-float pixel row reads.
// Also zeroes the K padding [588, 592) for this strip's 26 rows.
// ---------------------------------------------------------------------------
__global__ void prep_a(const float* __restrict__ pix) {
    const int b = blockIdx.x, ph = blockIdx.y;
    const float* src = pix + (size_t)b * (kC * kHW * kHW)
                       + (size_t)(ph * kPatch) * kHW;
    const int mbase = b * kP + ph * kNPS;
    constexpr int TOT = kC * kPatch * (kHW / 2);  // 7644 half2 elements
    for (int e = threadIdx.x; e < TOT; e += blockDim.x) {
        const int rowid = e / (kHW / 2);          // c*14 + ky
        const int x2 = e - rowid * (kHW / 2);
        const int c = rowid / kPatch;
        const int ky = rowid - c * kPatch;
        const int x = x2 * 2;
        const int pw = x / kPatch;
        const int kx = x - pw * kPatch;
        const float2 v = *reinterpret_cast<const float2*>(
            src + (size_t)c * (kHW * kHW) + ky * kHW + x);
        const int m = mbase + pw;
        const int k = c * (kPatch * kPatch) + ky * kPatch + kx;
        *reinterpret_cast<__half2*>(g_Ah + (size_t)m * kKpad + k) =
            __floats2half2_rn(v.x, v.y);
    }
    // K padding for this strip
    if (threadIdx.x < kNPS * 2) {
        const int m = mbase + (threadIdx.x >> 1);
        const int k = kK + (threadIdx.x & 1) * 2;
        *reinterpret_cast<__half2*>(g_Ah + (size_t)m * kKpad + k) =
            __float2half2_rn(0.f);
    }
}

__global__ void prep_w(const float* __restrict__ wgt) {
    const int total = kD * kKpad;
    for (int idx = blockIdx.x * blockDim.x + threadIdx.x; idx < total;
         idx += gridDim.x * blockDim.x) {
        const int n = idx / kKpad;
        const int k = idx - n * kKpad;
        g_Wh[idx] = __float2half_rn((k < kK) ? wgt[(size_t)n * kK + k] : 0.f);
    }
}

// ---------------------------------------------------------------------------
// GEMM: 128x192 tile, 16 warps (warp tile 32x48), 4-stage mbarrier ring,
// double-buffered fragments.
// ---------------------------------------------------------------------------
__global__ void __launch_bounds__(NT_THREADS, 1)
gemm_kernel(const float* __restrict__ bias,
            const float* __restrict__ pe,
            float* __restrict__ out) {
    extern __shared__ char smem[];
    const uint32_t sbase = smem_u32(smem);
    const uint32_t dbase = sbase + BARS;
    const int tid = threadIdx.x;
    const int wid = tid >> 5;
    const int lane = tid & 31;

    const int m0 = blockIdx.x * BM;
    const int n0 = blockIdx.y * BN;

    const int warp_m = (wid & 3) * 32;   // 4 warps along M
    const int warp_n = (wid >> 2) * 48;  // 4 warps along N

    if (tid == 0) {
        #pragma unroll
        for (int s = 0; s < NSTG; s++) {
            mbar_init(sbase + 8 * s, NT_THREADS);
            mbar_init(sbase + 32 + 8 * s, NT_THREADS);
        }
    }
    __syncthreads();

    auto produce = [&](int j, int s) {
        const int k0 = j * BK;
        const bool fullw = (j < NCHUNK - 1);   // last chunk is 16-wide
        const uint32_t sb = dbase + s * STAGE;
        #pragma unroll
        for (int i = 0; i < 2; i++) {          // A: 128 rows x 8 cols of 16B
            const int idx = tid + NT_THREADS * i;
            const int row = idx >> 3, c = idx & 7;
            if (fullw || c < 2)
                cp16(sb + row * ROWB + c * 16,
                     g_Ah + (size_t)(m0 + row) * kKpad + k0 + c * 8);
        }
        #pragma unroll
        for (int i = 0; i < 3; i++) {          // B: 192 rows x 8 cols
            const int idx = tid + NT_THREADS * i;
            const int row = idx >> 3, c = idx & 7;
            if (fullw || c < 2)
                cp16(sb + ARR_A + row * ROWB + c * 16,
                     g_Wh + (size_t)(n0 + row) * kKpad + k0 + c * 8);
        }
        cp_mbar_arrive_noinc(sbase + 8 * s);
    };

    // ldmatrix per-thread offsets
    const int sel = lane >> 3, li = lane & 7;
    const int aRow = (sel & 1) * 8 + li;
    const int aC16 = (sel >> 1) * 16;
    const int bRow = (sel >> 1) * 8 + li;
    const int bC16 = (sel & 1) * 16;

    float acc[2][6][4];
    #pragma unroll
    for (int i = 0; i < 2; i++)
        #pragma unroll
        for (int j = 0; j < 6; j++)
            #pragma unroll
            for (int q = 0; q < 4; q++) acc[i][j][q] = 0.f;

    produce(0, 0);
    produce(1, 1);
    produce(2, 2);

    // double-buffered fragments
    uint32_t af[2][2][4], bf[2][3][4];

    auto load_frags = [&](uint32_t aBase, uint32_t bBase, int ks, int buf) {
        #pragma unroll
        for (int mt = 0; mt < 2; mt++)
            ldsm4(af[buf][mt], aBase + mt * 16 * ROWB + ks * 32);
        #pragma unroll
        for (int bt = 0; bt < 3; bt++)
            ldsm4(bf[buf][bt], bBase + bt * 16 * ROWB + ks * 32);
    };
    auto do_mma = [&](int buf) {
        #pragma unroll
        for (int mt = 0; mt < 2; mt++)
            #pragma unroll
            for (int nt = 0; nt < 6; nt++)
                mma16816(acc[mt][nt], af[buf][mt], &bf[buf][nt >> 1][(nt & 1) * 2]);
    };

    #pragma unroll 1
    for (int j = 0; j < NCHUNK; j++) {
        const int s = j & 3;

        // prefetch chunk j+3 (stage previously held chunk j-1)
        const int jp = j + 3;
        if (jp < NCHUNK) {
            const int sp = jp & 3;
            if (jp >= NSTG)
                mbar_wait(sbase + 32 + 8 * sp, ((jp >> 2) - 1) & 1);
            produce(jp, sp);
        }

        // consume chunk j with fragment double-buffering
        mbar_wait(sbase + 8 * s, (j >> 2) & 1);
        const uint32_t st = dbase + s * STAGE;
        const uint32_t aBase = st + (warp_m + aRow) * ROWB + aC16;
        const uint32_t bBase = st + ARR_A + (warp_n + bRow) * ROWB + bC16;
        if (j < NCHUNK - 1) {
            load_frags(aBase, bBase, 0, 0);
            #pragma unroll
            for (int ks = 0; ks < 4; ks++) {
                if (ks < 3) load_frags(aBase, bBase, ks + 1, (ks + 1) & 1);
                do_mma(ks & 1);
            }
        } else {
            load_frags(aBase, bBase, 0, 0);
            do_mma(0);                         // partial chunk: 16 wide
        }
        mbar_arrive(sbase + 32 + 8 * s);       // stage free
    }

    // ---------------- epilogue: + bias + pos_emb[pos[m]] --------------------
    const int r = lane >> 2, cg = lane & 3;
    #pragma unroll
    for (int mt = 0; mt < 2; mt++) {
        #pragma unroll
        for (int h = 0; h < 2; h++) {
            const int m = m0 + warp_m + mt * 16 + h * 8 + r;
            const float* per = pe + (size_t)g_pos[m] * kD;
            float* orow = out + (size_t)m * kD;
            #pragma unroll
            for (int nt = 0; nt < 6; nt++) {
                const int n = n0 + warp_n + nt * 8 + cg * 2;
                const float2 p = *reinterpret_cast<const float2*>(per + n);
                const float2 bv = *reinterpret_cast<const float2*>(bias + n);
                float2 v;
                v.x = acc[mt][nt][h * 2 + 0] + p.x + bv.x;
                v.y = acc[mt][nt][h * 2 + 1] + p.y + bv.y;
                *reinterpret_cast<float2*>(orow + n) = v;
            }
        }
    }
}

// ---------------------------------------------------------------------------
extern "C" void kernel_launch(void* const* d_in, const int* in_sizes, int n_in,
                              void* d_out, int out_size) {
    const float* pix          = (const float*)d_in[0];
    const unsigned char* mask = (const unsigned char*)d_in[1];
    const float* wgt          = (const float*)d_in[2];
    const float* bias         = (const float*)d_in[3];
    const float* pe           = (const float*)d_in[4];
    float* out                = (float*)d_out;

    pos_kernel<<<kB, 128>>>(mask);
    prep_w<<<720, 256>>>(wgt);
    dim3 agrid(kB, kNPS);
    prep_a<<<agrid, 256>>>(pix);

    static bool attr_set = false;
    if (!attr_set) {
        cudaFuncSetAttribute(gemm_kernel,
                             cudaFuncAttributeMaxDynamicSharedMemorySize,
                             SMEM_SZ);
        attr_set = true;
    }
    dim3 grid(kM / BM, kD / BN);  // (169, 6)
    gemm_kernel<<<grid, NT_THREADS, SMEM_SZ>>>(bias, pe, out);
}

// round 17
// speedup vs baseline: 1.5338x; 1.5338x over previous
#include <cuda_runtime.h>
#include <cuda_fp16.h>
#include <cstdint>

// ===========================================================================
// Idefics3VisionEmbeddings via single-term fp16 mma.sync (base sm_103 ISA).
//   out[m,n] = sum_k A[m,k]*W[n,k] + bias[n] + pos_emb[pos[m], n]
//   M=21632 (=169*128 exact), N=1152 (=4*288), K=588 (pad 592)
// fp16 inputs (rn), fp32 accumulate. Norm-ratio error ~3e-4 < 1e-3.
// Block tile 128x288, 384 threads / 12 warps (warp tile 64x48, 2Mx6N),
// BK=64 (last chunk 16), 3-stage mbarrier ring.
// R13 post-mortem: smem crossbar traffic must stay under tensor time;
// this config keeps the R7 traffic ratio while giving 3 warps/SMSP.
// ===========================================================================

namespace {
constexpr int kNPS = 26, kPatch = 14, kB = 32, kC = 3, kHW = 364, kD = 1152;
constexpr int kP = kNPS * kNPS;           // 676
constexpr int kK = kC * kPatch * kPatch;  // 588
constexpr int kM = kB * kP;               // 21632
constexpr int kKpad = 592;                // 37 * 16

constexpr int BM = 128, BN = 288, BK = 64;
constexpr int NCHUNK = 10;                // 9 full (64) + 1 partial (16)
constexpr int NT = 384;

// smem rows: 64 fp16 = 128 B, padded to 144 B (16B-aligned; conflict-free)
constexpr int ROWB = 144;
constexpr int ARR_A = BM * ROWB;          // 18432 B
constexpr int ARR_B = BN * ROWB;          // 41472 B
constexpr int STAGE = ARR_A + ARR_B;      // 59904 B
constexpr int NSTG = 3;
constexpr int BARS = 64;                  // full[3] @ +8s, empty[3] @ +32+8s
constexpr int SMEM_SZ = BARS + NSTG * STAGE;  // 179776
}  // namespace

// -------------------- device scratch (no cudaMalloc allowed) ---------------
__device__ __align__(256) __half g_Ah[(size_t)kM * kKpad];
__device__ __align__(256) __half g_Wh[(size_t)kD * kKpad];
__device__ int g_pos[kM];

// -------------------- helpers ----------------------------------------------
__device__ __forceinline__ uint32_t smem_u32(const void* p) {
    uint32_t a;
    asm("{ .reg .u64 t; cvta.to.shared.u64 t, %1; cvt.u32.u64 %0, t; }"
        : "=r"(a) : "l"(p));
    return a;
}
__device__ __forceinline__ void cp16(uint32_t dst, const void* src) {
    asm volatile("cp.async.cg.shared.global [%0], [%1], 16;"
                 :: "r"(dst), "l"(src) : "memory");
}
__device__ __forceinline__ void cp_mbar_arrive_noinc(uint32_t bar) {
    asm volatile("cp.async.mbarrier.arrive.noinc.shared::cta.b64 [%0];"
                 :: "r"(bar) : "memory");
}
__device__ __forceinline__ void mbar_init(uint32_t a, uint32_t cnt) {
    asm volatile("mbarrier.init.shared.b64 [%0], %1;" :: "r"(a), "r"(cnt) : "memory");
}
__device__ __forceinline__ void mbar_arrive(uint32_t a) {
    asm volatile("mbarrier.arrive.shared.b64 _, [%0];" :: "r"(a) : "memory");
}
__device__ __forceinline__ void mbar_wait(uint32_t a, uint32_t parity) {
    asm volatile(
        "{\n .reg .pred P;\n"
        "WL_%=:\n"
        " mbarrier.try_wait.parity.shared.b64 P, [%0], %1, 0x989680;\n"
        " @P bra WD_%=;\n"
        " bra WL_%=;\n"
        "WD_%=:\n}" :: "r"(a), "r"(parity) : "memory");
}
__device__ __forceinline__ void ldsm4(uint32_t* r, uint32_t addr) {
    asm volatile("ldmatrix.sync.aligned.m8n8.x4.shared.b16 {%0,%1,%2,%3}, [%4];"
                 : "=r"(r[0]), "=r"(r[1]), "=r"(r[2]), "=r"(r[3]) : "r"(addr));
}
__device__ __forceinline__ void mma16816(float* c, const uint32_t* a,
                                         const uint32_t* b) {
    asm volatile(
        "mma.sync.aligned.m16n8k16.row.col.f32.f16.f16.f32 "
        "{%0,%1,%2,%3}, {%4,%5,%6,%7}, {%8,%9}, {%0,%1,%2,%3};"
        : "+f"(c[0]), "+f"(c[1]), "+f"(c[2]), "+f"(c[3])
        : "r"(a[0]), "r"(a[1]), "r"(a[2]), "r"(a[3]), "r"(b[0]), "r"(b[1]));
}

// ---------------------------------------------------------------------------
// Position ids (exact fp32 replica of the reference). Mask dtype auto-detect:
// byte 1 nonzero => u8/bool layout (nb_w>=13 guarantees mask[0][0][1]==1).
// ---------------------------------------------------------------------------
__global__ void pos_kernel(const unsigned char* __restrict__ mraw) {
    const int b = blockIdx.x;
    const int t = threadIdx.x;
    __shared__ int s_bh[kNPS], s_bw[kNPS];
    __shared__ int s_nbh, s_nbw;

    const bool is_u8 = (mraw[1] != 0);
    auto mval = [&](int idx) -> int {
        return is_u8 ? (int)mraw[idx] : (int)mraw[4 * (size_t)idx];
    };
    const int base = b * kP;
    if (t == 0) {
        int nh = 0, nw = 0;
        for (int i = 0; i < kNPS; i++) nh += (mval(base + i * kNPS) != 0);
        for (int j = 0; j < kNPS; j++) nw += (mval(base + j) != 0);
        s_nbh = nh; s_nbw = nw;
    }
    __syncthreads();
    if (t < kNPS) {
        const float eps = 1.0f - 1e-6f;
        const float fh = ((float)t / (float)s_nbh) * eps;
        const float fw = ((float)t / (float)s_nbw) * eps;
        int ch = 0, cw = 0;
        #pragma unroll
        for (int j = 1; j < kNPS; j++) {
            const float bnd = (float)j / (float)kNPS;
            ch += (bnd <= fh) ? 1 : 0;
            cw += (bnd <= fw) ? 1 : 0;
        }
        s_bh[t] = ch; s_bw[t] = cw;
    }
    __syncthreads();
    for (int p = t; p < kP; p += blockDim.x) {
        const int ph = p / kNPS;
        const int pw = p - ph * kNPS;
        g_pos[base + p] = (mval(base + p) != 0) ? (s_bh[ph] * kNPS + s_bw[pw]) : 0;
    }
}

// ---------------------------------------------------------------------------
// Prep A: one block per (b, ph) strip. Coalesced pixel-row reads; also zeroes
// the K padding [588, 592) for the strip's 26 rows.
// ---------------------------------------------------------------------------
__global__ void prep_a(const float* __restrict__ pix) {
    const int b = blockIdx.x, ph = blockIdx.y;
    const float* src = pix + (size_t)b * (kC * kHW * kHW)
                       + (size_t)(ph * kPatch) * kHW;
    const int mbase = b * kP + ph * kNPS;
    constexpr int TOT = kC * kPatch * (kHW / 2);  // 7644 half2 elements
    for (int e = threadIdx.x; e < TOT; e += blockDim.x) {
        const int rowid = e / (kHW / 2);          // c*14 + ky
        const int x2 = e - rowid * (kHW / 2);
        const int c = rowid / kPatch;
        const int ky = rowid - c * kPatch;
        const int x = x2 * 2;
        const int pw = x / kPatch;
        const int kx = x - pw * kPatch;
        const float2 v = *reinterpret_cast<const float2*>(
            src + (size_t)c * (kHW * kHW) + ky * kHW + x);
        const int m = mbase + pw;
        const int k = c * (kPatch * kPatch) + ky * kPatch + kx;
        *reinterpret_cast<__half2*>(g_Ah + (size_t)m * kKpad + k) =
            __floats2half2_rn(v.x, v.y);
    }
    if (threadIdx.x < kNPS * 2) {
        const int m = mbase + (threadIdx.x >> 1);
        const int k = kK + (threadIdx.x & 1) * 2;
        *reinterpret_cast<__half2*>(g_Ah + (size_t)m * kKpad + k) =
            __float2half2_rn(0.f);
    }
}

__global__ void prep_w(const float* __restrict__ wgt) {
    const int total = kD * kKpad;
    for (int idx = blockIdx.x * blockDim.x + threadIdx.x; idx < total;
         idx += gridDim.x * blockDim.x) {
        const int n = idx / kKpad;
        const int k = idx - n * kKpad;
        g_Wh[idx] = __float2half_rn((k < kK) ? wgt[(size_t)n * kK + k] : 0.f);
    }
}

// ---------------------------------------------------------------------------
// GEMM: 128x288 tile, 12 warps (warp tile 64x48, 2Mx6N), 3-stage ring.
// ---------------------------------------------------------------------------
__global__ void __launch_bounds__(NT, 1)
gemm_kernel(const float* __restrict__ bias,
            const float* __restrict__ pe,
            float* __restrict__ out) {
    extern __shared__ char smem[];
    const uint32_t sbase = smem_u32(smem);
    const uint32_t dbase = sbase + BARS;
    const int tid = threadIdx.x;
    const int wid = tid >> 5;
    const int lane = tid & 31;

    const int m0 = blockIdx.x * BM;
    const int n0 = blockIdx.y * BN;

    const int warp_m = (wid & 1) * 64;   // 2 warps along M
    const int warp_n = (wid >> 1) * 48;  // 6 warps along N

    if (tid == 0) {
        #pragma unroll
        for (int s = 0; s < NSTG; s++) {
            mbar_init(sbase + 8 * s, NT);
            mbar_init(sbase + 32 + 8 * s, NT);
        }
    }
    __syncthreads();

    auto produce = [&](int j, int s) {
        const int k0 = j * BK;
        const bool fullw = (j < NCHUNK - 1);   // last chunk is 16-wide
        const uint32_t sb = dbase + s * STAGE;
        #pragma unroll
        for (int i = 0; i < 3; i++) {          // A: 128 rows x 8 cols (1024)
            const int idx = tid + NT * i;
            const int row = idx >> 3, c = idx & 7;
            if (idx < BM * 8 && (fullw || c < 2))
                cp16(sb + row * ROWB + c * 16,
                     g_Ah + (size_t)(m0 + row) * kKpad + k0 + c * 8);
        }
        #pragma unroll
        for (int i = 0; i < 6; i++) {          // B: 288 rows x 8 cols (2304)
            const int idx = tid + NT * i;
            const int row = idx >> 3, c = idx & 7;
            if (fullw || c < 2)
                cp16(sb + ARR_A + row * ROWB + c * 16,
                     g_Wh + (size_t)(n0 + row) * kKpad + k0 + c * 8);
        }
        cp_mbar_arrive_noinc(sbase + 8 * s);
    };

    // ldmatrix per-thread offsets
    const int sel = lane >> 3, li = lane & 7;
    const int aRow = (sel & 1) * 8 + li;
    const int aC16 = (sel >> 1) * 16;
    const int bRow = (sel >> 1) * 8 + li;
    const int bC16 = (sel & 1) * 16;

    float acc[4][6][4];
    #pragma unroll
    for (int i = 0; i < 4; i++)
        #pragma unroll
        for (int j = 0; j < 6; j++)
            #pragma unroll
            for (int q = 0; q < 4; q++) acc[i][j][q] = 0.f;

    produce(0, 0);
    produce(1, 1);

    auto do_ks = [&](uint32_t aBase, uint32_t bBase, int ks) {
        uint32_t af[4][4], bf[3][4];
        #pragma unroll
        for (int mt = 0; mt < 4; mt++)
            ldsm4(af[mt], aBase + mt * 16 * ROWB + ks * 32);
        #pragma unroll
        for (int bt = 0; bt < 3; bt++)
            ldsm4(bf[bt], bBase + bt * 16 * ROWB + ks * 32);
        #pragma unroll
        for (int mt = 0; mt < 4; mt++)
            #pragma unroll
            for (int nt = 0; nt < 6; nt++)
                mma16816(acc[mt][nt], af[mt], &bf[nt >> 1][(nt & 1) * 2]);
    };

    #pragma unroll 1
    for (int j = 0; j < NCHUNK; j++) {
        const int s = j % 3;

        // prefetch chunk j+2 (stage previously held chunk j-1)
        const int jp = j + 2;
        if (jp < NCHUNK) {
            const int sp = jp % 3;
            if (jp >= NSTG)
                mbar_wait(sbase + 32 + 8 * sp, ((jp / 3) - 1) & 1);
            produce(jp, sp);
        }

        // consume chunk j
        mbar_wait(sbase + 8 * s, (j / 3) & 1);
        const uint32_t st = dbase + s * STAGE;
        const uint32_t aBase = st + (warp_m + aRow) * ROWB + aC16;
        const uint32_t bBase = st + ARR_A + (warp_n + bRow) * ROWB + bC16;
        if (j < NCHUNK - 1) {
            #pragma unroll
            for (int ks = 0; ks < 4; ks++) do_ks(aBase, bBase, ks);
        } else {
            do_ks(aBase, bBase, 0);            // partial chunk: 16 wide
        }
        mbar_arrive(sbase + 32 + 8 * s);       // stage free
    }

    // ---------------- epilogue: + bias + pos_emb[pos[m]] --------------------
    const int r = lane >> 2, cg = lane & 3;
    #pragma unroll
    for (int mt = 0; mt < 4; mt++) {
        #pragma unroll
        for (int h = 0; h < 2; h++) {
            const int m = m0 + warp_m + mt * 16 + h * 8 + r;
            const float* per = pe + (size_t)g_pos[m] * kD;
            float* orow = out + (size_t)m * kD;
            #pragma unroll
            for (int nt = 0; nt < 6; nt++) {
                const int n = n0 + warp_n + nt * 8 + cg * 2;
                const float2 p = *reinterpret_cast<const float2*>(per + n);
                const float2 bv = *reinterpret_cast<const float2*>(bias + n);
                float2 v;
                v.x = acc[mt][nt][h * 2 + 0] + p.x + bv.x;
                v.y = acc[mt][nt][h * 2 + 1] + p.y + bv.y;
                *reinterpret_cast<float2*>(orow + n) = v;
            }
        }
    }
}

// ---------------------------------------------------------------------------
extern "C" void kernel_launch(void* const* d_in, const int* in_sizes, int n_in,
                              void* d_out, int out_size) {
    const float* pix          = (const float*)d_in[0];
    const unsigned char* mask = (const unsigned char*)d_in[1];
    const float* wgt          = (const float*)d_in[2];
    const float* bias         = (const float*)d_in[3];
    const float* pe           = (const float*)d_in[4];
    float* out                = (float*)d_out;

    pos_kernel<<<kB, 128>>>(mask);
    prep_w<<<720, 256>>>(wgt);
    dim3 agrid(kB, kNPS);
    prep_a<<<agrid, 256>>>(pix);

    static bool attr_set = false;
    if (!attr_set) {
        cudaFuncSetAttribute(gemm_kernel,
                             cudaFuncAttributeMaxDynamicSharedMemorySize,
                             SMEM_SZ);
        attr_set = true;
    }
    dim3 grid(kM / BM, kD / BN);  // (169, 4)
    gemm_kernel<<<grid, NT, SMEM_SZ>>>(bias, pe, out);
}